// round 1
// baseline (speedup 1.0000x reference)
#include <cuda_runtime.h>
#include <cstdint>

#define B_ 4
#define S_ 2048
#define D_ 1024
#define H_ 16
#define DH_ 64
#define MROWS (B_ * S_)          // 8192
#define QKV_ELEMS (B_ * H_ * S_ * DH_)   // 8388608
#define C_ELEMS   (B_ * S_ * D_)         // 8388608

// -------- scratch (static device arrays; no allocation) --------
__device__ float g_q[QKV_ELEMS];
__device__ float g_k[QKV_ELEMS];
__device__ float g_v[QKV_ELEMS];
__device__ float g_c[C_ELEMS];

// -------- f32x2 packed helpers --------
__device__ __forceinline__ void fma2(unsigned long long &d, unsigned long long a, unsigned long long b) {
    asm("fma.rn.f32x2 %0, %1, %2, %3;" : "=l"(d) : "l"(a), "l"(b), "l"(d));
}
__device__ __forceinline__ unsigned long long bcast2(float x) {
    unsigned long long r;
    asm("mov.b64 %0, {%1, %2};" : "=l"(r) : "f"(x), "f"(x));
    return r;
}
__device__ __forceinline__ float lo2(unsigned long long v) {
    return __uint_as_float((unsigned)(v & 0xffffffffull));
}
__device__ __forceinline__ float hi2(unsigned long long v) {
    return __uint_as_float((unsigned)(v >> 32));
}

// ============================================================
// Kernel 1: fused per-head QKV projection.
//   q[b,h,s,e] = sum_d x[b,s,d] * Wq[h,d,e]   (q additionally * 1/8)
// GEMM: M=8192 (b,s), K=1024 (d), N=64 per head (e). grid=(64,H,3)
// BM=128, BN=64, BK=16, 256 thr, thread tile 8x4 as f32x2 row-pairs.
// ============================================================
__global__ __launch_bounds__(256) void qkv_proj_kernel(
    const float* __restrict__ x,
    const float* __restrict__ Wq,
    const float* __restrict__ Wk,
    const float* __restrict__ Wv)
{
    const int z = blockIdx.z;
    const float* W = (z == 0) ? Wq : ((z == 1) ? Wk : Wv);
    float* out = (z == 0) ? g_q : ((z == 1) ? g_k : g_v);
    const float scale = (z == 0) ? 0.125f : 1.0f;

    const int h  = blockIdx.y;
    const int m0 = blockIdx.x * 128;

    __shared__ float Xs[16][136];   // transposed: Xs[k][m]
    __shared__ float Ws[16][72];    // Ws[k][n]

    const int tid = threadIdx.x;
    const int tyr = tid >> 4;   // 0..15 -> rows tyr*8 .. +7
    const int txc = tid & 15;   // 0..15 -> cols txc*4 .. +3

    unsigned long long acc[4][4];
    #pragma unroll
    for (int p = 0; p < 4; ++p)
        #pragma unroll
        for (int c = 0; c < 4; ++c) acc[p][c] = 0ull;

    const float* Wh = W + (size_t)h * D_ * DH_;

    for (int kt = 0; kt < D_ / 16; ++kt) {
        const int k0 = kt * 16;
        // load X tile 128x16 (2 float4 per thread), store transposed
        #pragma unroll
        for (int it = 0; it < 2; ++it) {
            int f  = tid + it * 256;
            int r  = f >> 2;
            int c4 = f & 3;
            float4 v = *(const float4*)(x + (size_t)(m0 + r) * D_ + k0 + c4 * 4);
            Xs[c4 * 4 + 0][r] = v.x;
            Xs[c4 * 4 + 1][r] = v.y;
            Xs[c4 * 4 + 2][r] = v.z;
            Xs[c4 * 4 + 3][r] = v.w;
        }
        // load W tile 16x64 (1 float4 per thread)
        {
            int r  = tid >> 4;
            int e4 = tid & 15;
            float4 v = *(const float4*)(Wh + (size_t)(k0 + r) * DH_ + e4 * 4);
            *(float4*)&Ws[r][e4 * 4] = v;
        }
        __syncthreads();

        #pragma unroll
        for (int k = 0; k < 16; ++k) {
            unsigned long long a2[4];
            #pragma unroll
            for (int p = 0; p < 4; ++p)
                a2[p] = *(const unsigned long long*)&Xs[k][tyr * 8 + 2 * p];
            unsigned long long b2[4];
            #pragma unroll
            for (int c = 0; c < 4; ++c)
                b2[c] = bcast2(Ws[k][txc * 4 + c]);
            #pragma unroll
            for (int p = 0; p < 4; ++p)
                #pragma unroll
                for (int c = 0; c < 4; ++c)
                    fma2(acc[p][c], a2[p], b2[c]);
        }
        __syncthreads();
    }

    // epilogue: out[((b*H+h)*S + s)*DH + e]
    #pragma unroll
    for (int p = 0; p < 4; ++p) {
        int rlo = m0 + tyr * 8 + 2 * p;
        int rhi = rlo + 1;
        float4 vlo, vhi;
        vlo.x = lo2(acc[p][0]) * scale; vlo.y = lo2(acc[p][1]) * scale;
        vlo.z = lo2(acc[p][2]) * scale; vlo.w = lo2(acc[p][3]) * scale;
        vhi.x = hi2(acc[p][0]) * scale; vhi.y = hi2(acc[p][1]) * scale;
        vhi.z = hi2(acc[p][2]) * scale; vhi.w = hi2(acc[p][3]) * scale;
        {
            int b = rlo >> 11, s = rlo & 2047;
            *(float4*)(out + (((size_t)(b * H_ + h) * S_ + s) * DH_) + txc * 4) = vlo;
        }
        {
            int b = rhi >> 11, s = rhi & 2047;
            *(float4*)(out + (((size_t)(b * H_ + h) * S_ + s) * DH_) + txc * 4) = vhi;
        }
    }
}

// ============================================================
// Kernel 2: causal flash attention, fp32.
// One block = 64 query rows of one (b,h). 128 threads.
// Thread: rows (rp, rp+32), score cols c = q4+4j, out cols e = q4*16+i.
// ============================================================
#define LDT 68
#define ATTN_SMEM (4 * 64 * LDT * 4)

__global__ __launch_bounds__(128) void attn_kernel()
{
    extern __shared__ float sm[];
    float* Qs = sm;
    float* Ks = sm + 64 * LDT;
    float* Vs = sm + 2 * 64 * LDT;
    float* Ps = sm + 3 * 64 * LDT;

    const int tid = threadIdx.x;
    const int rp  = tid >> 2;   // 0..31
    const int q4  = tid & 3;    // 0..3
    const int rA  = rp;
    const int rB  = rp + 32;

    const int bh = blockIdx.y;              // b*H + h
    const int qt = (gridDim.x - 1) - blockIdx.x;  // big tiles first

    // load Q tile (64x64)
    const float* qg = g_q + ((size_t)bh * S_ + qt * 64) * DH_;
    for (int idx = tid; idx < 1024; idx += 128) {
        int row = idx >> 4, c4 = idx & 15;
        float4 v = *(const float4*)(qg + (size_t)row * DH_ + c4 * 4);
        *(float4*)&Qs[row * LDT + c4 * 4] = v;
    }

    float mA = -3.0e38f, mB = -3.0e38f;
    float lA = 0.f, lB = 0.f;
    float oA[16], oB[16];
    #pragma unroll
    for (int i = 0; i < 16; ++i) { oA[i] = 0.f; oB[i] = 0.f; }

    for (int kt = 0; kt <= qt; ++kt) {
        __syncthreads();  // prev PV / Q load done before overwriting K,V
        const float* kg = g_k + ((size_t)bh * S_ + kt * 64) * DH_;
        const float* vg = g_v + ((size_t)bh * S_ + kt * 64) * DH_;
        for (int idx = tid; idx < 1024; idx += 128) {
            int row = idx >> 4, c4 = idx & 15;
            float4 kv = *(const float4*)(kg + (size_t)row * DH_ + c4 * 4);
            *(float4*)&Ks[row * LDT + c4 * 4] = kv;
            float4 vv = *(const float4*)(vg + (size_t)row * DH_ + c4 * 4);
            *(float4*)&Vs[row * LDT + c4 * 4] = vv;
        }
        __syncthreads();

        // ---- scores S = Q K^T ----
        float sA[16], sB[16];
        #pragma unroll
        for (int j = 0; j < 16; ++j) { sA[j] = 0.f; sB[j] = 0.f; }

        #pragma unroll 4
        for (int e0 = 0; e0 < 64; e0 += 4) {
            float4 qa = *(const float4*)&Qs[rA * LDT + e0];
            float4 qb = *(const float4*)&Qs[rB * LDT + e0];
            #pragma unroll
            for (int j = 0; j < 16; ++j) {
                int c = q4 + 4 * j;
                float4 kk = *(const float4*)&Ks[c * LDT + e0];
                sA[j] += qa.x * kk.x + qa.y * kk.y + qa.z * kk.z + qa.w * kk.w;
                sB[j] += qb.x * kk.x + qb.y * kk.y + qb.z * kk.z + qb.w * kk.w;
            }
        }

        if (kt == qt) {  // causal mask inside diagonal tile
            #pragma unroll
            for (int j = 0; j < 16; ++j) {
                int c = q4 + 4 * j;
                if (c > rA) sA[j] = -3.0e38f;
                if (c > rB) sB[j] = -3.0e38f;
            }
        }

        // ---- online softmax (rows owned by 4-thread quads) ----
        float mtA = -3.0e38f, mtB = -3.0e38f;
        #pragma unroll
        for (int j = 0; j < 16; ++j) { mtA = fmaxf(mtA, sA[j]); mtB = fmaxf(mtB, sB[j]); }
        mtA = fmaxf(mtA, __shfl_xor_sync(0xffffffffu, mtA, 1));
        mtA = fmaxf(mtA, __shfl_xor_sync(0xffffffffu, mtA, 2));
        mtB = fmaxf(mtB, __shfl_xor_sync(0xffffffffu, mtB, 1));
        mtB = fmaxf(mtB, __shfl_xor_sync(0xffffffffu, mtB, 2));

        float mnA = fmaxf(mA, mtA);
        float mnB = fmaxf(mB, mtB);
        float corrA = __expf(mA - mnA);
        float corrB = __expf(mB - mnB);

        float rsA = 0.f, rsB = 0.f;
        #pragma unroll
        for (int j = 0; j < 16; ++j) {
            float pa = __expf(sA[j] - mnA); sA[j] = pa; rsA += pa;
            float pb = __expf(sB[j] - mnB); sB[j] = pb; rsB += pb;
        }
        rsA += __shfl_xor_sync(0xffffffffu, rsA, 1);
        rsA += __shfl_xor_sync(0xffffffffu, rsA, 2);
        rsB += __shfl_xor_sync(0xffffffffu, rsB, 1);
        rsB += __shfl_xor_sync(0xffffffffu, rsB, 2);

        lA = lA * corrA + rsA;
        lB = lB * corrB + rsB;
        #pragma unroll
        for (int i = 0; i < 16; ++i) { oA[i] *= corrA; oB[i] *= corrB; }
        mA = mnA; mB = mnB;

        #pragma unroll
        for (int j = 0; j < 16; ++j) {
            int c = q4 + 4 * j;
            Ps[rA * LDT + c] = sA[j];
            Ps[rB * LDT + c] = sB[j];
        }
        __syncthreads();

        // ---- O += P V ----
        #pragma unroll 4
        for (int c = 0; c < 64; ++c) {
            float pa = Ps[rA * LDT + c];
            float pb = Ps[rB * LDT + c];
            #pragma unroll
            for (int ii = 0; ii < 4; ++ii) {
                float4 v4 = *(const float4*)&Vs[c * LDT + q4 * 16 + 4 * ii];
                oA[4 * ii + 0] += pa * v4.x; oA[4 * ii + 1] += pa * v4.y;
                oA[4 * ii + 2] += pa * v4.z; oA[4 * ii + 3] += pa * v4.w;
                oB[4 * ii + 0] += pb * v4.x; oB[4 * ii + 1] += pb * v4.y;
                oB[4 * ii + 2] += pb * v4.z; oB[4 * ii + 3] += pb * v4.w;
            }
        }
    }

    // finalize: concat layout g_c[b, s, h*DH + e]
    const float invA = 1.0f / lA;
    const float invB = 1.0f / lB;
    const int b = bh >> 4, h = bh & 15;
    float* cA = g_c + ((size_t)b * S_ + (qt * 64 + rA)) * D_ + h * DH_ + q4 * 16;
    float* cB = g_c + ((size_t)b * S_ + (qt * 64 + rB)) * D_ + h * DH_ + q4 * 16;
    #pragma unroll
    for (int ii = 0; ii < 4; ++ii) {
        float4 wa, wb;
        wa.x = oA[4 * ii + 0] * invA; wa.y = oA[4 * ii + 1] * invA;
        wa.z = oA[4 * ii + 2] * invA; wa.w = oA[4 * ii + 3] * invA;
        wb.x = oB[4 * ii + 0] * invB; wb.y = oB[4 * ii + 1] * invB;
        wb.z = oB[4 * ii + 2] * invB; wb.w = oB[4 * ii + 3] * invB;
        *(float4*)(cA + 4 * ii) = wa;
        *(float4*)(cB + 4 * ii) = wb;
    }
}

// ============================================================
// Kernel 3: output projection out = concat @ Wo + bo
// M=8192, K=1024, N=1024 (col tiles of 64). grid=(64,16)
// ============================================================
__global__ __launch_bounds__(256) void out_proj_kernel(
    const float* __restrict__ Wo,
    const float* __restrict__ bo,
    float* __restrict__ out)
{
    const int n0 = blockIdx.y * 64;
    const int m0 = blockIdx.x * 128;

    __shared__ float Xs[16][136];
    __shared__ float Ws[16][72];

    const int tid = threadIdx.x;
    const int tyr = tid >> 4;
    const int txc = tid & 15;

    unsigned long long acc[4][4];
    #pragma unroll
    for (int p = 0; p < 4; ++p)
        #pragma unroll
        for (int c = 0; c < 4; ++c) acc[p][c] = 0ull;

    for (int kt = 0; kt < D_ / 16; ++kt) {
        const int k0 = kt * 16;
        #pragma unroll
        for (int it = 0; it < 2; ++it) {
            int f  = tid + it * 256;
            int r  = f >> 2;
            int c4 = f & 3;
            float4 v = *(const float4*)(g_c + (size_t)(m0 + r) * D_ + k0 + c4 * 4);
            Xs[c4 * 4 + 0][r] = v.x;
            Xs[c4 * 4 + 1][r] = v.y;
            Xs[c4 * 4 + 2][r] = v.z;
            Xs[c4 * 4 + 3][r] = v.w;
        }
        {
            int r  = tid >> 4;
            int e4 = tid & 15;
            float4 v = *(const float4*)(Wo + (size_t)(k0 + r) * D_ + n0 + e4 * 4);
            *(float4*)&Ws[r][e4 * 4] = v;
        }
        __syncthreads();

        #pragma unroll
        for (int k = 0; k < 16; ++k) {
            unsigned long long a2[4];
            #pragma unroll
            for (int p = 0; p < 4; ++p)
                a2[p] = *(const unsigned long long*)&Xs[k][tyr * 8 + 2 * p];
            unsigned long long b2[4];
            #pragma unroll
            for (int c = 0; c < 4; ++c)
                b2[c] = bcast2(Ws[k][txc * 4 + c]);
            #pragma unroll
            for (int p = 0; p < 4; ++p)
                #pragma unroll
                for (int c = 0; c < 4; ++c)
                    fma2(acc[p][c], a2[p], b2[c]);
        }
        __syncthreads();
    }

    float4 bias = *(const float4*)(bo + n0 + txc * 4);
    #pragma unroll
    for (int p = 0; p < 4; ++p) {
        int rlo = m0 + tyr * 8 + 2 * p;
        int rhi = rlo + 1;
        float4 vlo, vhi;
        vlo.x = lo2(acc[p][0]) + bias.x; vlo.y = lo2(acc[p][1]) + bias.y;
        vlo.z = lo2(acc[p][2]) + bias.z; vlo.w = lo2(acc[p][3]) + bias.w;
        vhi.x = hi2(acc[p][0]) + bias.x; vhi.y = hi2(acc[p][1]) + bias.y;
        vhi.z = hi2(acc[p][2]) + bias.z; vhi.w = hi2(acc[p][3]) + bias.w;
        *(float4*)(out + (size_t)rlo * D_ + n0 + txc * 4) = vlo;
        *(float4*)(out + (size_t)rhi * D_ + n0 + txc * 4) = vhi;
    }
}

// ============================================================
extern "C" void kernel_launch(void* const* d_in, const int* in_sizes, int n_in,
                              void* d_out, int out_size)
{
    const float* x  = (const float*)d_in[0];
    const float* Wq = (const float*)d_in[1];
    const float* Wk = (const float*)d_in[2];
    const float* Wv = (const float*)d_in[3];
    const float* Wo = (const float*)d_in[4];
    const float* bo = (const float*)d_in[5];
    float* out = (float*)d_out;

    cudaFuncSetAttribute(attn_kernel, cudaFuncAttributeMaxDynamicSharedMemorySize, ATTN_SMEM);

    qkv_proj_kernel<<<dim3(MROWS / 128, H_, 3), 256>>>(x, Wq, Wk, Wv);
    attn_kernel<<<dim3(S_ / 64, B_ * H_), 128, ATTN_SMEM>>>();
    out_proj_kernel<<<dim3(MROWS / 128, D_ / 64), 256>>>(Wo, bo, out);
}